// round 14
// baseline (speedup 1.0000x reference)
#include <cuda_runtime.h>
#include <cuda_bf16.h>
#include <cstdint>

#define SEQL 2048
#define DH 64
#define BQ 128
#define BK 128
#define NT 16

__device__ float g_rowsum[2 * 16 * SEQL];

// K1 smem: Q hi/lo, double-buffered K hi/lo, double-buffered mask bits, rowsum
#define QH1 0
#define QL1 18432
#define KB1 36864           // + b*36864 ; KH=+0, KL=+18432
#define MB1 110592          // + b*2048  ; 128 rows x 4 uint32
#define RS1 114688
#define K1TOT 115200
// K2 smem: transposed V hi/lo + inv
#define VH2 0
#define VL2 17408
#define INV2 34816
#define K2TOT 35360

static __device__ __forceinline__ float fexp8(float x) {  // exp(x/8), FMA-pipe, clamped
    float t = x * 0.18033688011112042f;
    t = fminf(fmaxf(t, -126.0f), 126.0f);
    float kf = t + 12582912.0f;
    float f = t - (kf - 12582912.0f);
    int ki = __float_as_int(kf) << 23;
    float p = 1.3333558146e-3f;
    p = fmaf(p, f, 9.6181291076e-3f);
    p = fmaf(p, f, 5.55041086648e-2f);
    p = fmaf(p, f, 2.402265069591e-1f);
    p = fmaf(p, f, 6.931471805599e-1f);
    p = fmaf(p, f, 1.0f);
    return __int_as_float(__float_as_int(p) + ki);
}

static __device__ __forceinline__ void split2(float a, float b, uint32_t& hi, uint32_t& lo) {
    __nv_bfloat16 ha = __float2bfloat16_rn(a), hb = __float2bfloat16_rn(b);
    hi = (uint32_t)__bfloat16_as_ushort(ha) | ((uint32_t)__bfloat16_as_ushort(hb) << 16);
    lo = (uint32_t)__bfloat16_as_ushort(__float2bfloat16_rn(a - __bfloat162float(ha))) |
         ((uint32_t)__bfloat16_as_ushort(__float2bfloat16_rn(b - __bfloat162float(hb))) << 16);
}

static __device__ __forceinline__ void mma16816(float* c, const uint32_t* a, uint32_t b0, uint32_t b1) {
    asm volatile(
        "mma.sync.aligned.m16n8k16.row.col.f32.bf16.bf16.f32 "
        "{%0,%1,%2,%3}, {%4,%5,%6,%7}, {%8,%9}, {%0,%1,%2,%3};"
        : "+f"(c[0]), "+f"(c[1]), "+f"(c[2]), "+f"(c[3])
        : "r"(a[0]), "r"(a[1]), "r"(a[2]), "r"(a[3]), "r"(b0), "r"(b1));
}

static __device__ __forceinline__ void stage64(char* sm, int oh, int ol, const float* g, int tid) {
    for (int i = tid; i < 2048; i += 256) {
        int r = i >> 4, c = (i & 15) * 4;
        float4 x = __ldg((const float4*)(g + r * 64 + c));
        uint32_t h0, l0, h1, l1;
        split2(x.x, x.y, h0, l0); split2(x.z, x.w, h1, l1);
        *(uint2*)(sm + oh + r * 144 + c * 2) = make_uint2(h0, h1);
        *(uint2*)(sm + ol + r * 144 + c * 2) = make_uint2(l0, l1);
    }
}

static __device__ __forceinline__ uint32_t pack4(uint32_t u) {  // 4 bool bytes -> 4 bits
    return (u & 1u) | ((u >> 7) & 2u) | ((u >> 14) & 4u) | ((u >> 21) & 8u);
}

// build 128x128 bit-mask (128 rows x 4 words) for tile t into buffer b
static __device__ __forceinline__ void stage_mbits(char* sm, int b, const unsigned char* mg8,
                                                   const uint32_t* mg32, int t, int tid, bool isInt) {
    uint32_t* mb = (uint32_t*)(sm + MB1 + b * 2048);
    if (!isInt) {
        for (int widx = tid; widx < 512; widx += 256) {
            int r = widx >> 2, cw = widx & 3;
            const uint4* p = (const uint4*)(mg8 + (size_t)r * SEQL + t * BK + cw * 32);
            uint4 u0 = __ldg(p), u1 = __ldg(p + 1);
            uint32_t wv = pack4(u0.x) | (pack4(u0.y) << 4) | (pack4(u0.z) << 8) | (pack4(u0.w) << 12)
                        | (pack4(u1.x) << 16) | (pack4(u1.y) << 20) | (pack4(u1.z) << 24) | (pack4(u1.w) << 28);
            mb[widx] = wv;
        }
    } else {
        for (int widx = tid; widx < 512; widx += 256) {
            int r = widx >> 2, cw = widx & 3;
            const uint4* p = (const uint4*)(mg32 + (size_t)r * SEQL + t * BK + cw * 32);
            uint32_t wv = 0;
#pragma unroll
            for (int j = 0; j < 8; ++j) {
                uint4 u = __ldg(p + j);
                wv |= ((u.x != 0u) ? 1u : 0u) << (4 * j);
                wv |= ((u.y != 0u) ? 1u : 0u) << (4 * j + 1);
                wv |= ((u.z != 0u) ? 1u : 0u) << (4 * j + 2);
                wv |= ((u.w != 0u) ? 1u : 0u) << (4 * j + 3);
            }
            mb[widx] = wv;
        }
    }
}

__global__ void __launch_bounds__(256, 2)
k1_qk_exp(const float* __restrict__ q, const float* __restrict__ k,
          const unsigned char* __restrict__ mask, float* __restrict__ attn) {
    extern __shared__ char sm[];
    const int tid = threadIdx.x, lane = tid & 31, w = tid >> 5;
    const int g = lane >> 2, t4 = lane & 3, wm = w >> 1, wn = w & 1;
    const int qt = blockIdx.x, bh = blockIdx.y, b = bh >> 4, qb = qt * BQ;
    const float* qg = q + ((size_t)bh * SEQL + qb) * DH;
    const float* kg = k + (size_t)bh * SEQL * DH;
    const unsigned char* mg8 = mask + ((size_t)b * SEQL + qb) * SEQL;
    const uint32_t* mg32 = (const uint32_t*)mask + ((size_t)b * SEQL + qb) * SEQL;
    float* ag = attn + ((size_t)bh * SEQL + qb) * SEQL;
    float* rs = (float*)(sm + RS1);
    if (tid < 128) rs[tid] = 0.f;
    // per-thread mask dtype probe (uniform; no smem race)
    bool isInt;
    {
        const uint32_t* mw = (const uint32_t*)mask;
        uint32_t big = 0;
#pragma unroll
        for (int i = 0; i < 16; ++i) big |= (__ldg(mw + i) > 1u) ? 1u : 0u;
        isInt = (big == 0u);
    }
    stage64(sm, QH1, QL1, qg, tid);
    stage64(sm, KB1, KB1 + 18432, kg, tid);
    stage_mbits(sm, 0, mg8, mg32, 0, tid, isInt);
    __syncthreads();

    float rsum[4] = {0.f, 0.f, 0.f, 0.f};

    for (int t = 0; t < NT; ++t) {
        const int cur = t & 1;
        if (t + 1 < NT) {  // stage next tile concurrently with this tile's MMA
            stage64(sm, KB1 + (cur ^ 1) * 36864, KB1 + (cur ^ 1) * 36864 + 18432,
                    kg + (size_t)(t + 1) * BK * DH, tid);
            stage_mbits(sm, cur ^ 1, mg8, mg32, t + 1, tid, isInt);
        }

        float acc[2][8][4];
#pragma unroll
        for (int mf = 0; mf < 2; ++mf)
#pragma unroll
            for (int nf = 0; nf < 8; ++nf)
#pragma unroll
                for (int e = 0; e < 4; ++e) acc[mf][nf][e] = 0.f;

        const int KH = KB1 + cur * 36864, KL = KH + 18432;
#pragma unroll
        for (int ks = 0; ks < 4; ++ks) {
            uint32_t ah[2][4], al[2][4];
#pragma unroll
            for (int mf = 0; mf < 2; ++mf) {
                int rb = (wm * 32 + mf * 16 + g) * 144 + ks * 32 + t4 * 4;
                ah[mf][0] = *(uint32_t*)(sm + QH1 + rb);
                ah[mf][1] = *(uint32_t*)(sm + QH1 + rb + 8 * 144);
                ah[mf][2] = *(uint32_t*)(sm + QH1 + rb + 16);
                ah[mf][3] = *(uint32_t*)(sm + QH1 + rb + 8 * 144 + 16);
                al[mf][0] = *(uint32_t*)(sm + QL1 + rb);
                al[mf][1] = *(uint32_t*)(sm + QL1 + rb + 8 * 144);
                al[mf][2] = *(uint32_t*)(sm + QL1 + rb + 16);
                al[mf][3] = *(uint32_t*)(sm + QL1 + rb + 8 * 144 + 16);
            }
#pragma unroll
            for (int nf = 0; nf < 8; ++nf) {
                int cb = (wn * 64 + nf * 8 + g) * 144 + ks * 32 + t4 * 4;
                uint32_t bh0 = *(uint32_t*)(sm + KH + cb), bh1 = *(uint32_t*)(sm + KH + cb + 16);
                uint32_t bl0 = *(uint32_t*)(sm + KL + cb), bl1 = *(uint32_t*)(sm + KL + cb + 16);
#pragma unroll
                for (int mf = 0; mf < 2; ++mf) {
                    mma16816(acc[mf][nf], ah[mf], bh0, bh1);
                    mma16816(acc[mf][nf], ah[mf], bl0, bl1);
                    mma16816(acc[mf][nf], al[mf], bh0, bh1);
                }
            }
        }

        const uint32_t* mb = (const uint32_t*)(sm + MB1 + cur * 2048);
#pragma unroll
        for (int mf = 0; mf < 2; ++mf) {
            int r0 = wm * 32 + mf * 16 + g;
            uint32_t wa0 = mb[r0 * 4 + wn * 2], wa1 = mb[r0 * 4 + wn * 2 + 1];
            uint32_t wb0 = mb[(r0 + 8) * 4 + wn * 2], wb1 = mb[(r0 + 8) * 4 + wn * 2 + 1];
#pragma unroll
            for (int nf = 0; nf < 8; ++nf) {
                int c0 = wn * 64 + nf * 8 + t4 * 2;
                int sh = (nf & 3) * 8 + t4 * 2;
                uint32_t ma = ((nf >> 2) ? wa1 : wa0) >> sh;
                uint32_t mbv = ((nf >> 2) ? wb1 : wb0) >> sh;
                float e0 = (ma & 1u)  ? fexp8(acc[mf][nf][0]) : 1.0f;
                float e1 = (ma & 2u)  ? fexp8(acc[mf][nf][1]) : 1.0f;
                float e2 = (mbv & 1u) ? fexp8(acc[mf][nf][2]) : 1.0f;
                float e3 = (mbv & 2u) ? fexp8(acc[mf][nf][3]) : 1.0f;
                rsum[mf * 2] += e0 + e1;
                rsum[mf * 2 + 1] += e2 + e3;
                float* d = ag + (size_t)r0 * SEQL + t * BK + c0;
                __stcs((float2*)d, make_float2(e0, e1));
                __stcs((float2*)(d + 8 * SEQL), make_float2(e2, e3));
            }
        }
        __syncthreads();
    }

#pragma unroll
    for (int i = 0; i < 4; ++i) {
        rsum[i] += __shfl_xor_sync(~0u, rsum[i], 1);
        rsum[i] += __shfl_xor_sync(~0u, rsum[i], 2);
    }
    if (t4 == 0) {
        atomicAdd(&rs[wm * 32 + g], rsum[0]);
        atomicAdd(&rs[wm * 32 + g + 8], rsum[1]);
        atomicAdd(&rs[wm * 32 + 16 + g], rsum[2]);
        atomicAdd(&rs[wm * 32 + 24 + g], rsum[3]);
    }
    __syncthreads();
    if (tid < 128) g_rowsum[(size_t)bh * SEQL + qb + tid] = rs[tid];
}

// K2: M-only warp partition; P lives in registers (gmem -> frag direct)
__global__ void __launch_bounds__(256, 2)
k2_norm_pv(const float* __restrict__ v, float* __restrict__ attn, float* __restrict__ ctx) {
    extern __shared__ char sm[];
    const int tid = threadIdx.x, lane = tid & 31, w = tid >> 5;
    const int g = lane >> 2, t4 = lane & 3;
    const int qt = blockIdx.x, bh = blockIdx.y, qb = qt * BQ;
    float* ag = attn + ((size_t)bh * SEQL + qb) * SEQL;
    const float* vg = v + (size_t)bh * SEQL * DH;
    float* inv = (float*)(sm + INV2);
    if (tid < 128)
        inv[tid] = 1.0f / fmaxf(g_rowsum[(size_t)bh * SEQL + qb + tid], 1e-30f);

    const int r0 = w * 16 + g, r1 = r0 + 8;   // local q-rows owned by this thread
    float* er0 = ag + (size_t)r0 * SEQL;
    float* er1 = ag + (size_t)r1 * SEQL;

    float acc[8][4];
#pragma unroll
    for (int nf = 0; nf < 8; ++nf)
#pragma unroll
        for (int e = 0; e < 4; ++e) acc[nf][e] = 0.f;

    for (int t = 0; t < NT; ++t) {
        __syncthreads();  // prior tile's MMA done with V (and inv ready at t=0)
        // stage V^T hi/lo (conflict-free key-pair packing)
        for (int i = tid; i < 1024; i += 256) {
            int kp = i & 63, dm = i >> 6;
            const float* vb = vg + (size_t)(t * BK + 2 * kp) * DH + dm * 4;
            float4 xa = __ldg((const float4*)vb);
            float4 xb = __ldg((const float4*)(vb + DH));
            float fa[4] = {xa.x, xa.y, xa.z, xa.w}, fb[4] = {xb.x, xb.y, xb.z, xb.w};
#pragma unroll
            for (int j = 0; j < 4; ++j) {
                uint32_t hi, lo;
                split2(fa[j], fb[j], hi, lo);
                *(uint32_t*)(sm + VH2 + (dm * 4 + j) * 272 + kp * 4) = hi;
                *(uint32_t*)(sm + VL2 + (dm * 4 + j) * 272 + kp * 4) = lo;
            }
        }
        __syncthreads();
        const float il0 = inv[r0], il1 = inv[r1];

        // software-pipelined k-chunks of 32 (2 ks-fragments each)
        float2 ec[8], en[8];
        {
            int cb = t * BK + t4 * 2;
#pragma unroll
            for (int s = 0; s < 4; ++s) {
                ec[s]     = __ldcs((const float2*)(er0 + cb + s * 8));
                ec[4 + s] = __ldcs((const float2*)(er1 + cb + s * 8));
            }
        }
#pragma unroll
        for (int kc = 0; kc < 4; ++kc) {
            if (kc < 3) {
                int cb = t * BK + (kc + 1) * 32 + t4 * 2;
#pragma unroll
                for (int s = 0; s < 4; ++s) {
                    en[s]     = __ldcs((const float2*)(er0 + cb + s * 8));
                    en[4 + s] = __ldcs((const float2*)(er1 + cb + s * 8));
                }
            }
            // normalize, write attention, split to fragments
            uint32_t ah[8], al[8];
            int cb = t * BK + kc * 32 + t4 * 2;
#pragma unroll
            for (int s = 0; s < 4; ++s) {
                float2 p0 = ec[s], p1 = ec[4 + s];
                p0.x *= il0; p0.y *= il0;
                p1.x *= il1; p1.y *= il1;
                __stcs((float2*)(er0 + cb + s * 8), p0);
                __stcs((float2*)(er1 + cb + s * 8), p1);
                split2(p0.x, p0.y, ah[s], al[s]);
                split2(p1.x, p1.y, ah[4 + s], al[4 + s]);
            }
#pragma unroll
            for (int ksl = 0; ksl < 2; ++ksl) {
                uint32_t Ah[4] = {ah[2 * ksl], ah[4 + 2 * ksl], ah[2 * ksl + 1], ah[5 + 2 * ksl]};
                uint32_t Al[4] = {al[2 * ksl], al[4 + 2 * ksl], al[2 * ksl + 1], al[5 + 2 * ksl]};
#pragma unroll
                for (int nf = 0; nf < 8; ++nf) {
                    int db = (nf * 8 + g) * 272 + (kc * 32 + ksl * 16) * 2 + t4 * 4;
                    uint32_t bh0 = *(uint32_t*)(sm + VH2 + db), bh1 = *(uint32_t*)(sm + VH2 + db + 16);
                    uint32_t bl0 = *(uint32_t*)(sm + VL2 + db), bl1 = *(uint32_t*)(sm + VL2 + db + 16);
                    mma16816(acc[nf], Ah, bh0, bh1);
                    mma16816(acc[nf], Ah, bl0, bl1);
                    mma16816(acc[nf], Al, bh0, bh1);
                }
            }
#pragma unroll
            for (int s = 0; s < 8; ++s) ec[s] = en[s];
        }
    }

    float* co = ctx + ((size_t)bh * SEQL + qb) * DH;
#pragma unroll
    for (int nf = 0; nf < 8; ++nf) {
        int d0 = nf * 8 + t4 * 2;
        *(float2*)(co + (size_t)r0 * DH + d0) = make_float2(acc[nf][0], acc[nf][1]);
        *(float2*)(co + (size_t)r1 * DH + d0) = make_float2(acc[nf][2], acc[nf][3]);
    }
}

extern "C" void kernel_launch(void* const* d_in, const int* in_sizes, int n_in,
                              void* d_out, int out_size) {
    const float* q = (const float*)d_in[0];
    const float* k = (const float*)d_in[1];
    const float* v = (const float*)d_in[2];
    const unsigned char* mask = (const unsigned char*)d_in[3];
    float* out = (float*)d_out;
    float* out_ctx = out;
    float* out_attn = out + (size_t)2 * 16 * SEQL * DH;

    cudaFuncSetAttribute(k1_qk_exp, cudaFuncAttributeMaxDynamicSharedMemorySize, K1TOT);
    cudaFuncSetAttribute(k2_norm_pv, cudaFuncAttributeMaxDynamicSharedMemorySize, K2TOT);
    dim3 grid(SEQL / BQ, 32);
    k1_qk_exp<<<grid, 256, K1TOT>>>(q, k, mask, out_attn);
    k2_norm_pv<<<grid, 256, K2TOT>>>(v, out_attn, out_ctx);
}

// round 15
// speedup vs baseline: 1.1602x; 1.1602x over previous
#include <cuda_runtime.h>
#include <cuda_bf16.h>
#include <cuda_fp16.h>
#include <cstdint>

#define SEQL 2048
#define DH 64
#define BQ 128
#define BK 128
#define NT 16

__device__ float g_rowsum[2 * 16 * SEQL];

#define K1_QH 0
#define K1_QL 18432
#define K1_KH 36864
#define K1_KL 55296
#define K1_MS 73728
#define K1_RS 90112
#define K1_FLG 90624
#define K1_TOT 90656
// K2: P fp16 (128x136, stride 272B), V^T fp16 hi/lo, inv
#define K2_P  0
#define K2_VH 34816
#define K2_VL 52224
#define K2_INV 69632
#define K2_TOT 70144

static __device__ __forceinline__ float fexp8(float x) {  // exp(x/8), FMA-pipe, clamped
    float t = x * 0.18033688011112042f;
    t = fminf(fmaxf(t, -126.0f), 126.0f);
    float kf = t + 12582912.0f;
    float f = t - (kf - 12582912.0f);
    int ki = __float_as_int(kf) << 23;
    float p = 1.3333558146e-3f;
    p = fmaf(p, f, 9.6181291076e-3f);
    p = fmaf(p, f, 5.55041086648e-2f);
    p = fmaf(p, f, 2.402265069591e-1f);
    p = fmaf(p, f, 6.931471805599e-1f);
    p = fmaf(p, f, 1.0f);
    return __int_as_float(__float_as_int(p) + ki);
}

static __device__ __forceinline__ void split2(float a, float b, uint32_t& hi, uint32_t& lo) {
    __nv_bfloat16 ha = __float2bfloat16_rn(a), hb = __float2bfloat16_rn(b);
    hi = (uint32_t)__bfloat16_as_ushort(ha) | ((uint32_t)__bfloat16_as_ushort(hb) << 16);
    lo = (uint32_t)__bfloat16_as_ushort(__float2bfloat16_rn(a - __bfloat162float(ha))) |
         ((uint32_t)__bfloat16_as_ushort(__float2bfloat16_rn(b - __bfloat162float(hb))) << 16);
}

static __device__ __forceinline__ uint32_t packh2(float a, float b) {
    __half2 h = __floats2half2_rn(a, b);
    return *(uint32_t*)&h;
}
static __device__ __forceinline__ void split2h(float a, float b, uint32_t& hi, uint32_t& lo) {
    __half ha = __float2half_rn(a), hb = __float2half_rn(b);
    hi = (uint32_t)__half_as_ushort(ha) | ((uint32_t)__half_as_ushort(hb) << 16);
    lo = (uint32_t)__half_as_ushort(__float2half_rn(a - __half2float(ha))) |
         ((uint32_t)__half_as_ushort(__float2half_rn(b - __half2float(hb))) << 16);
}

static __device__ __forceinline__ void mma16816(float* c, const uint32_t* a, uint32_t b0, uint32_t b1) {
    asm volatile(
        "mma.sync.aligned.m16n8k16.row.col.f32.bf16.bf16.f32 "
        "{%0,%1,%2,%3}, {%4,%5,%6,%7}, {%8,%9}, {%0,%1,%2,%3};"
        : "+f"(c[0]), "+f"(c[1]), "+f"(c[2]), "+f"(c[3])
        : "r"(a[0]), "r"(a[1]), "r"(a[2]), "r"(a[3]), "r"(b0), "r"(b1));
}
static __device__ __forceinline__ void mma16816h(float* c, const uint32_t* a, uint32_t b0, uint32_t b1) {
    asm volatile(
        "mma.sync.aligned.m16n8k16.row.col.f32.f16.f16.f32 "
        "{%0,%1,%2,%3}, {%4,%5,%6,%7}, {%8,%9}, {%0,%1,%2,%3};"
        : "+f"(c[0]), "+f"(c[1]), "+f"(c[2]), "+f"(c[3])
        : "r"(a[0]), "r"(a[1]), "r"(a[2]), "r"(a[3]), "r"(b0), "r"(b1));
}

static __device__ __forceinline__ void stage64(char* sm, int oh, int ol, const float* g, int tid) {
    for (int i = tid; i < 2048; i += 256) {
        int r = i >> 4, c = (i & 15) * 4;
        float4 x = __ldg((const float4*)(g + r * 64 + c));
        uint32_t h0, l0, h1, l1;
        split2(x.x, x.y, h0, l0); split2(x.z, x.w, h1, l1);
        *(uint2*)(sm + oh + r * 144 + c * 2) = make_uint2(h0, h1);
        *(uint2*)(sm + ol + r * 144 + c * 2) = make_uint2(l0, l1);
    }
}

__global__ void __launch_bounds__(256, 2)
k1_qk_exp(const float* __restrict__ q, const float* __restrict__ k,
          const unsigned char* __restrict__ mask, float* __restrict__ attn) {
    extern __shared__ char sm[];
    const int tid = threadIdx.x, lane = tid & 31, w = tid >> 5;
    const int g = lane >> 2, t4 = lane & 3, wm = w >> 1, wn = w & 1;
    const int qt = blockIdx.x, bh = blockIdx.y, b = bh >> 4, qb = qt * BQ;
    const float* qg = q + ((size_t)bh * SEQL + qb) * DH;
    const float* kg = k + (size_t)bh * SEQL * DH;
    const unsigned char* mg8 = mask + ((size_t)b * SEQL + qb) * SEQL;
    const uint32_t* mg32 = (const uint32_t*)mask + ((size_t)b * SEQL + qb) * SEQL;
    float* ag = attn + ((size_t)bh * SEQL + qb) * SEQL;
    float* rs = (float*)(sm + K1_RS);
    if (tid < 128) rs[tid] = 0.f;
    if (tid == 0) {
        const uint32_t* mw = (const uint32_t*)mask;
        uint32_t big = 0;
        for (int i = 0; i < 16; ++i) big |= (__ldg(mw + i) > 1u) ? 1u : 0u;
        *(int*)(sm + K1_FLG) = big ? 0 : 1;
    }
    stage64(sm, K1_QH, K1_QL, qg, tid);

    float rsum[4] = {0.f, 0.f, 0.f, 0.f};

    for (int t = 0; t < NT; ++t) {
        __syncthreads();
        stage64(sm, K1_KH, K1_KL, kg + (size_t)t * BK * DH, tid);
        if (*(const int*)(sm + K1_FLG)) {
            for (int i = tid; i < 4096; i += 256) {
                int r = i >> 5, c4 = (i & 31) * 4;
                uint4 wv = __ldg((const uint4*)(mg32 + (size_t)r * SEQL + t * BK + c4));
                *(uchar4*)(sm + K1_MS + r * 128 + c4) =
                    make_uchar4(wv.x != 0, wv.y != 0, wv.z != 0, wv.w != 0);
            }
        } else {
            for (int i = tid; i < 1024; i += 256) {
                int r = i >> 3, c = (i & 7) * 16;
                *(uint4*)(sm + K1_MS + r * 128 + c) =
                    __ldg((const uint4*)(mg8 + (size_t)r * SEQL + t * BK + c));
            }
        }
        __syncthreads();

        float acc[2][8][4];
#pragma unroll
        for (int mf = 0; mf < 2; ++mf)
#pragma unroll
            for (int nf = 0; nf < 8; ++nf)
#pragma unroll
                for (int e = 0; e < 4; ++e) acc[mf][nf][e] = 0.f;

#pragma unroll
        for (int ks = 0; ks < 4; ++ks) {
            uint32_t ah[2][4], al[2][4];
#pragma unroll
            for (int mf = 0; mf < 2; ++mf) {
                int rb = (wm * 32 + mf * 16 + g) * 144 + ks * 32 + t4 * 4;
                ah[mf][0] = *(uint32_t*)(sm + K1_QH + rb);
                ah[mf][1] = *(uint32_t*)(sm + K1_QH + rb + 8 * 144);
                ah[mf][2] = *(uint32_t*)(sm + K1_QH + rb + 16);
                ah[mf][3] = *(uint32_t*)(sm + K1_QH + rb + 8 * 144 + 16);
                al[mf][0] = *(uint32_t*)(sm + K1_QL + rb);
                al[mf][1] = *(uint32_t*)(sm + K1_QL + rb + 8 * 144);
                al[mf][2] = *(uint32_t*)(sm + K1_QL + rb + 16);
                al[mf][3] = *(uint32_t*)(sm + K1_QL + rb + 8 * 144 + 16);
            }
#pragma unroll
            for (int nf = 0; nf < 8; ++nf) {
                int cb = (wn * 64 + nf * 8 + g) * 144 + ks * 32 + t4 * 4;
                uint32_t bh0 = *(uint32_t*)(sm + K1_KH + cb), bh1 = *(uint32_t*)(sm + K1_KH + cb + 16);
                uint32_t bl0 = *(uint32_t*)(sm + K1_KL + cb), bl1 = *(uint32_t*)(sm + K1_KL + cb + 16);
#pragma unroll
                for (int mf = 0; mf < 2; ++mf) {
                    mma16816(acc[mf][nf], ah[mf], bh0, bh1);
                    mma16816(acc[mf][nf], ah[mf], bl0, bl1);
                    mma16816(acc[mf][nf], al[mf], bh0, bh1);
                }
            }
        }

#pragma unroll
        for (int mf = 0; mf < 2; ++mf)
#pragma unroll
            for (int nf = 0; nf < 8; ++nf) {
                int r0 = wm * 32 + mf * 16 + g, c0 = wn * 64 + nf * 8 + t4 * 2;
                unsigned m01 = *(unsigned short*)(sm + K1_MS + r0 * 128 + c0);
                unsigned m23 = *(unsigned short*)(sm + K1_MS + (r0 + 8) * 128 + c0);
                float e0 = (m01 & 0xffu) ? fexp8(acc[mf][nf][0]) : 1.0f;
                float e1 = (m01 >> 8)    ? fexp8(acc[mf][nf][1]) : 1.0f;
                float e2 = (m23 & 0xffu) ? fexp8(acc[mf][nf][2]) : 1.0f;
                float e3 = (m23 >> 8)    ? fexp8(acc[mf][nf][3]) : 1.0f;
                rsum[mf * 2] += e0 + e1;
                rsum[mf * 2 + 1] += e2 + e3;
                float* d = ag + (size_t)r0 * SEQL + t * BK + c0;
                __stcs((float2*)d, make_float2(e0, e1));
                __stcs((float2*)(d + 8 * SEQL), make_float2(e2, e3));
            }
    }

#pragma unroll
    for (int i = 0; i < 4; ++i) {
        rsum[i] += __shfl_xor_sync(~0u, rsum[i], 1);
        rsum[i] += __shfl_xor_sync(~0u, rsum[i], 2);
    }
    if (t4 == 0) {
        atomicAdd(&rs[wm * 32 + g], rsum[0]);
        atomicAdd(&rs[wm * 32 + g + 8], rsum[1]);
        atomicAdd(&rs[wm * 32 + 16 + g], rsum[2]);
        atomicAdd(&rs[wm * 32 + 24 + g], rsum[3]);
    }
    __syncthreads();
    if (tid < 128) g_rowsum[(size_t)bh * SEQL + qb + tid] = rs[tid];
}

__global__ void __launch_bounds__(256, 2)
k2_norm_pv(const float* __restrict__ v, float* __restrict__ attn, float* __restrict__ ctx) {
    extern __shared__ char sm[];
    const int tid = threadIdx.x, lane = tid & 31, w = tid >> 5;
    const int g = lane >> 2, t4 = lane & 3, wm = w >> 1, wn = w & 1;
    const int qt = blockIdx.x, bh = blockIdx.y, qb = qt * BQ;
    float* ag = attn + ((size_t)bh * SEQL + qb) * SEQL;
    const float* vg = v + (size_t)bh * SEQL * DH;
    float* inv = (float*)(sm + K2_INV);
    if (tid < 128)
        inv[tid] = 1.0f / fmaxf(g_rowsum[(size_t)bh * SEQL + qb + tid], 1e-30f);

    float acc[2][4][4];
#pragma unroll
    for (int mf = 0; mf < 2; ++mf)
#pragma unroll
        for (int nf = 0; nf < 4; ++nf)
#pragma unroll
            for (int e = 0; e < 4; ++e) acc[mf][nf][e] = 0.f;

    for (int t = 0; t < NT; ++t) {
        __syncthreads();
        // normalize e -> attention (.cs) + stage fp16 P; batched loads (MLP=4)
#pragma unroll
        for (int ii = 0; ii < 16; ii += 4) {
            float4 e4[4];
            int rr[4], cc[4];
#pragma unroll
            for (int j = 0; j < 4; ++j) {
                int i = (ii + j) * 256 + tid;
                rr[j] = i >> 5; cc[j] = (i & 31) * 4;
                e4[j] = *(const float4*)(ag + (size_t)rr[j] * SEQL + t * BK + cc[j]);
            }
#pragma unroll
            for (int j = 0; j < 4; ++j) {
                float il = inv[rr[j]];
                float4 e = e4[j];
                e.x *= il; e.y *= il; e.z *= il; e.w *= il;
                __stcs((float4*)(ag + (size_t)rr[j] * SEQL + t * BK + cc[j]), e);
                *(uint2*)(sm + K2_P + rr[j] * 272 + cc[j] * 2) =
                    make_uint2(packh2(e.x, e.y), packh2(e.z, e.w));
            }
        }
        // V^T staging: conflict-free key-pair fp16 hi/lo
        for (int i = tid; i < 1024; i += 256) {
            int kp = i & 63, dm = i >> 6;
            const float* vb = vg + (size_t)(t * BK + 2 * kp) * DH + dm * 4;
            float4 xa = __ldg((const float4*)vb);
            float4 xb = __ldg((const float4*)(vb + DH));
            float fa[4] = {xa.x, xa.y, xa.z, xa.w}, fb[4] = {xb.x, xb.y, xb.z, xb.w};
#pragma unroll
            for (int j = 0; j < 4; ++j) {
                uint32_t hi, lo;
                split2h(fa[j], fb[j], hi, lo);
                *(uint32_t*)(sm + K2_VH + (dm * 4 + j) * 272 + kp * 4) = hi;
                *(uint32_t*)(sm + K2_VL + (dm * 4 + j) * 272 + kp * 4) = lo;
            }
        }
        __syncthreads();

#pragma unroll
        for (int ks = 0; ks < 8; ++ks) {
            uint32_t ah[2][4];
#pragma unroll
            for (int mf = 0; mf < 2; ++mf) {
                int rb = (wm * 32 + mf * 16 + g) * 272 + ks * 32 + t4 * 4;
                ah[mf][0] = *(uint32_t*)(sm + K2_P + rb);
                ah[mf][1] = *(uint32_t*)(sm + K2_P + rb + 8 * 272);
                ah[mf][2] = *(uint32_t*)(sm + K2_P + rb + 16);
                ah[mf][3] = *(uint32_t*)(sm + K2_P + rb + 8 * 272 + 16);
            }
#pragma unroll
            for (int nf = 0; nf < 4; ++nf) {
                int db = (wn * 32 + nf * 8 + g) * 272 + ks * 32 + t4 * 4;
                uint32_t bh0 = *(uint32_t*)(sm + K2_VH + db), bh1 = *(uint32_t*)(sm + K2_VH + db + 16);
                uint32_t bl0 = *(uint32_t*)(sm + K2_VL + db), bl1 = *(uint32_t*)(sm + K2_VL + db + 16);
#pragma unroll
                for (int mf = 0; mf < 2; ++mf) {
                    mma16816h(acc[mf][nf], ah[mf], bh0, bh1);
                    mma16816h(acc[mf][nf], ah[mf], bl0, bl1);
                }
            }
        }
    }
#pragma unroll
    for (int mf = 0; mf < 2; ++mf)
#pragma unroll
        for (int nf = 0; nf < 4; ++nf) {
            int r0 = qb + wm * 32 + mf * 16 + g, d0 = wn * 32 + nf * 8 + t4 * 2;
            float* o = ctx + ((size_t)bh * SEQL + r0) * DH + d0;
            *(float2*)o = make_float2(acc[mf][nf][0], acc[mf][nf][1]);
            *(float2*)(o + 8 * DH) = make_float2(acc[mf][nf][2], acc[mf][nf][3]);
        }
}

extern "C" void kernel_launch(void* const* d_in, const int* in_sizes, int n_in,
                              void* d_out, int out_size) {
    const float* q = (const float*)d_in[0];
    const float* k = (const float*)d_in[1];
    const float* v = (const float*)d_in[2];
    const unsigned char* mask = (const unsigned char*)d_in[3];
    float* out = (float*)d_out;
    float* out_ctx = out;
    float* out_attn = out + (size_t)2 * 16 * SEQL * DH;

    cudaFuncSetAttribute(k1_qk_exp, cudaFuncAttributeMaxDynamicSharedMemorySize, K1_TOT);
    cudaFuncSetAttribute(k2_norm_pv, cudaFuncAttributeMaxDynamicSharedMemorySize, K2_TOT);
    dim3 grid(SEQL / BQ, 32);
    k1_qk_exp<<<grid, 256, K1_TOT>>>(q, k, mask, out_attn);
    k2_norm_pv<<<grid, 256, K2_TOT>>>(v, out_attn, out_ctx);
}

// round 16
// speedup vs baseline: 1.2793x; 1.1027x over previous
#include <cuda_runtime.h>
#include <cuda_bf16.h>
#include <cuda_fp16.h>
#include <cstdint>

#define SEQL 2048
#define DH 64
#define BQ 128
#define BK 128
#define NT 16

__device__ float g_rowsum[2 * 16 * SEQL];
__device__ uint32_t g_mbits[2 * SEQL * (SEQL / 32)];   // 1 MB packed mask bits

#define K1_QH 0
#define K1_QL 18432
#define K1_KH 36864
#define K1_KL 55296
#define K1_RS 73728
#define K1_TOT 74240
// K2: P fp16 (128x136, stride 272B), V^T fp16 hi/lo, inv
#define K2_P  0
#define K2_VH 34816
#define K2_VL 52224
#define K2_INV 69632
#define K2_TOT 70144

static __device__ __forceinline__ float fexp8m(float x) {  // exp(x/8) = 2^(x*log2e/8), 1 MUFU
    float t = x * 0.18033688011112042f;
    float r;
    asm("ex2.approx.f32 %0, %1;" : "=f"(r) : "f"(t));
    return r;
}

static __device__ __forceinline__ void split2(float a, float b, uint32_t& hi, uint32_t& lo) {
    __nv_bfloat16 ha = __float2bfloat16_rn(a), hb = __float2bfloat16_rn(b);
    hi = (uint32_t)__bfloat16_as_ushort(ha) | ((uint32_t)__bfloat16_as_ushort(hb) << 16);
    lo = (uint32_t)__bfloat16_as_ushort(__float2bfloat16_rn(a - __bfloat162float(ha))) |
         ((uint32_t)__bfloat16_as_ushort(__float2bfloat16_rn(b - __bfloat162float(hb))) << 16);
}

static __device__ __forceinline__ uint32_t packh2(float a, float b) {
    __half2 h = __floats2half2_rn(a, b);
    return *(uint32_t*)&h;
}
static __device__ __forceinline__ void split2h(float a, float b, uint32_t& hi, uint32_t& lo) {
    __half ha = __float2half_rn(a), hb = __float2half_rn(b);
    hi = (uint32_t)__half_as_ushort(ha) | ((uint32_t)__half_as_ushort(hb) << 16);
    lo = (uint32_t)__half_as_ushort(__float2half_rn(a - __half2float(ha))) |
         ((uint32_t)__half_as_ushort(__float2half_rn(b - __half2float(hb))) << 16);
}

static __device__ __forceinline__ void mma16816(float* c, const uint32_t* a, uint32_t b0, uint32_t b1) {
    asm volatile(
        "mma.sync.aligned.m16n8k16.row.col.f32.bf16.bf16.f32 "
        "{%0,%1,%2,%3}, {%4,%5,%6,%7}, {%8,%9}, {%0,%1,%2,%3};"
        : "+f"(c[0]), "+f"(c[1]), "+f"(c[2]), "+f"(c[3])
        : "r"(a[0]), "r"(a[1]), "r"(a[2]), "r"(a[3]), "r"(b0), "r"(b1));
}
static __device__ __forceinline__ void mma16816h(float* c, const uint32_t* a, uint32_t b0, uint32_t b1) {
    asm volatile(
        "mma.sync.aligned.m16n8k16.row.col.f32.f16.f16.f32 "
        "{%0,%1,%2,%3}, {%4,%5,%6,%7}, {%8,%9}, {%0,%1,%2,%3};"
        : "+f"(c[0]), "+f"(c[1]), "+f"(c[2]), "+f"(c[3])
        : "r"(a[0]), "r"(a[1]), "r"(a[2]), "r"(a[3]), "r"(b0), "r"(b1));
}

static __device__ __forceinline__ void stage64(char* sm, int oh, int ol, const float* g, int tid) {
    for (int i = tid; i < 2048; i += 256) {
        int r = i >> 4, c = (i & 15) * 4;
        float4 x = __ldg((const float4*)(g + r * 64 + c));
        uint32_t h0, l0, h1, l1;
        split2(x.x, x.y, h0, l0); split2(x.z, x.w, h1, l1);
        *(uint2*)(sm + oh + r * 144 + c * 2) = make_uint2(h0, h1);
        *(uint2*)(sm + ol + r * 144 + c * 2) = make_uint2(l0, l1);
    }
}

static __device__ __forceinline__ uint32_t pack4(uint32_t u) {  // 4 bool bytes -> 4 bits
    return (u & 1u) | ((u >> 7) & 2u) | ((u >> 14) & 4u) | ((u >> 21) & 8u);
}

// k0: pack mask (bool bytes or int32) into bits, 32 entries per thread
__global__ void __launch_bounds__(256)
k0_pack_mask(const unsigned char* __restrict__ mask) {
    const int idx = blockIdx.x * 256 + threadIdx.x;   // word index
    const uint32_t* mw = (const uint32_t*)mask;
    uint32_t big = 0;
#pragma unroll
    for (int i = 0; i < 16; ++i) big |= (__ldg(mw + i) > 1u) ? 1u : 0u;
    uint32_t wv = 0;
    if (big == 0u) {  // int32 mask
        const uint4* p = (const uint4*)(mw + (size_t)idx * 32);
#pragma unroll
        for (int j = 0; j < 8; ++j) {
            uint4 u = __ldg(p + j);
            wv |= ((u.x != 0u) ? 1u : 0u) << (4 * j);
            wv |= ((u.y != 0u) ? 1u : 0u) << (4 * j + 1);
            wv |= ((u.z != 0u) ? 1u : 0u) << (4 * j + 2);
            wv |= ((u.w != 0u) ? 1u : 0u) << (4 * j + 3);
        }
    } else {          // bool bytes
        const uint4* p = (const uint4*)(mask + (size_t)idx * 32);
        uint4 u0 = __ldg(p), u1 = __ldg(p + 1);
        wv = pack4(u0.x) | (pack4(u0.y) << 4) | (pack4(u0.z) << 8) | (pack4(u0.w) << 12)
           | (pack4(u1.x) << 16) | (pack4(u1.y) << 20) | (pack4(u1.z) << 24) | (pack4(u1.w) << 28);
    }
    g_mbits[idx] = wv;
}

__global__ void __launch_bounds__(256, 2)
k1_qk_exp(const float* __restrict__ q, const float* __restrict__ k,
          float* __restrict__ attn) {
    extern __shared__ char sm[];
    const int tid = threadIdx.x, lane = tid & 31, w = tid >> 5;
    const int g = lane >> 2, t4 = lane & 3, wm = w >> 1, wn = w & 1;
    const int qt = blockIdx.x, bh = blockIdx.y, b = bh >> 4, qb = qt * BQ;
    const float* qg = q + ((size_t)bh * SEQL + qb) * DH;
    const float* kg = k + (size_t)bh * SEQL * DH;
    const uint32_t* mb = g_mbits + (size_t)(b * SEQL + qb) * (SEQL / 32);
    float* ag = attn + ((size_t)bh * SEQL + qb) * SEQL;
    float* rs = (float*)(sm + K1_RS);
    if (tid < 128) rs[tid] = 0.f;
    stage64(sm, K1_QH, K1_QL, qg, tid);

    float rsum[4] = {0.f, 0.f, 0.f, 0.f};

    for (int t = 0; t < NT; ++t) {
        __syncthreads();
        stage64(sm, K1_KH, K1_KL, kg + (size_t)t * BK * DH, tid);
        __syncthreads();

        float acc[2][8][4];
#pragma unroll
        for (int mf = 0; mf < 2; ++mf)
#pragma unroll
            for (int nf = 0; nf < 8; ++nf)
#pragma unroll
                for (int e = 0; e < 4; ++e) acc[mf][nf][e] = 0.f;

#pragma unroll
        for (int ks = 0; ks < 4; ++ks) {
            uint32_t ah[2][4], al[2][4];
#pragma unroll
            for (int mf = 0; mf < 2; ++mf) {
                int rb = (wm * 32 + mf * 16 + g) * 144 + ks * 32 + t4 * 4;
                ah[mf][0] = *(uint32_t*)(sm + K1_QH + rb);
                ah[mf][1] = *(uint32_t*)(sm + K1_QH + rb + 8 * 144);
                ah[mf][2] = *(uint32_t*)(sm + K1_QH + rb + 16);
                ah[mf][3] = *(uint32_t*)(sm + K1_QH + rb + 8 * 144 + 16);
                al[mf][0] = *(uint32_t*)(sm + K1_QL + rb);
                al[mf][1] = *(uint32_t*)(sm + K1_QL + rb + 8 * 144);
                al[mf][2] = *(uint32_t*)(sm + K1_QL + rb + 16);
                al[mf][3] = *(uint32_t*)(sm + K1_QL + rb + 8 * 144 + 16);
            }
#pragma unroll
            for (int nf = 0; nf < 8; ++nf) {
                int cb = (wn * 64 + nf * 8 + g) * 144 + ks * 32 + t4 * 4;
                uint32_t bh0 = *(uint32_t*)(sm + K1_KH + cb), bh1 = *(uint32_t*)(sm + K1_KH + cb + 16);
                uint32_t bl0 = *(uint32_t*)(sm + K1_KL + cb), bl1 = *(uint32_t*)(sm + K1_KL + cb + 16);
#pragma unroll
                for (int mf = 0; mf < 2; ++mf) {
                    mma16816(acc[mf][nf], ah[mf], bh0, bh1);
                    mma16816(acc[mf][nf], ah[mf], bl0, bl1);
                    mma16816(acc[mf][nf], al[mf], bh0, bh1);
                }
            }
        }

#pragma unroll
        for (int mf = 0; mf < 2; ++mf) {
            int r0 = wm * 32 + mf * 16 + g;
            const uint32_t* ra = mb + (size_t)r0 * (SEQL / 32) + t * 4 + wn * 2;
            const uint32_t* rb2 = mb + (size_t)(r0 + 8) * (SEQL / 32) + t * 4 + wn * 2;
            uint32_t wa0 = __ldg(ra), wa1 = __ldg(ra + 1);
            uint32_t wb0 = __ldg(rb2), wb1 = __ldg(rb2 + 1);
#pragma unroll
            for (int nf = 0; nf < 8; ++nf) {
                int c0 = wn * 64 + nf * 8 + t4 * 2;
                int sh = (nf & 3) * 8 + t4 * 2;
                uint32_t ma = ((nf >> 2) ? wa1 : wa0) >> sh;
                uint32_t mbv = ((nf >> 2) ? wb1 : wb0) >> sh;
                float e0 = (ma & 1u)  ? fexp8m(acc[mf][nf][0]) : 1.0f;
                float e1 = (ma & 2u)  ? fexp8m(acc[mf][nf][1]) : 1.0f;
                float e2 = (mbv & 1u) ? fexp8m(acc[mf][nf][2]) : 1.0f;
                float e3 = (mbv & 2u) ? fexp8m(acc[mf][nf][3]) : 1.0f;
                rsum[mf * 2] += e0 + e1;
                rsum[mf * 2 + 1] += e2 + e3;
                float* d = ag + (size_t)r0 * SEQL + t * BK + c0;
                __stcs((float2*)d, make_float2(e0, e1));
                __stcs((float2*)(d + 8 * SEQL), make_float2(e2, e3));
            }
        }
    }

#pragma unroll
    for (int i = 0; i < 4; ++i) {
        rsum[i] += __shfl_xor_sync(~0u, rsum[i], 1);
        rsum[i] += __shfl_xor_sync(~0u, rsum[i], 2);
    }
    if (t4 == 0) {
        atomicAdd(&rs[wm * 32 + g], rsum[0]);
        atomicAdd(&rs[wm * 32 + g + 8], rsum[1]);
        atomicAdd(&rs[wm * 32 + 16 + g], rsum[2]);
        atomicAdd(&rs[wm * 32 + 24 + g], rsum[3]);
    }
    __syncthreads();
    if (tid < 128) g_rowsum[(size_t)bh * SEQL + qb + tid] = rs[tid];
}

__global__ void __launch_bounds__(256, 2)
k2_norm_pv(const float* __restrict__ v, float* __restrict__ attn, float* __restrict__ ctx) {
    extern __shared__ char sm[];
    const int tid = threadIdx.x, lane = tid & 31, w = tid >> 5;
    const int g = lane >> 2, t4 = lane & 3, wm = w >> 1, wn = w & 1;
    const int qt = blockIdx.x, bh = blockIdx.y, qb = qt * BQ;
    float* ag = attn + ((size_t)bh * SEQL + qb) * SEQL;
    const float* vg = v + (size_t)bh * SEQL * DH;
    float* inv = (float*)(sm + K2_INV);
    if (tid < 128)
        inv[tid] = 1.0f / fmaxf(g_rowsum[(size_t)bh * SEQL + qb + tid], 1e-30f);

    float acc[2][4][4];
#pragma unroll
    for (int mf = 0; mf < 2; ++mf)
#pragma unroll
        for (int nf = 0; nf < 4; ++nf)
#pragma unroll
            for (int e = 0; e < 4; ++e) acc[mf][nf][e] = 0.f;

    for (int t = 0; t < NT; ++t) {
        __syncthreads();
#pragma unroll
        for (int ii = 0; ii < 16; ii += 4) {
            float4 e4[4];
            int rr[4], cc[4];
#pragma unroll
            for (int j = 0; j < 4; ++j) {
                int i = (ii + j) * 256 + tid;
                rr[j] = i >> 5; cc[j] = (i & 31) * 4;
                e4[j] = *(const float4*)(ag + (size_t)rr[j] * SEQL + t * BK + cc[j]);
            }
#pragma unroll
            for (int j = 0; j < 4; ++j) {
                float il = inv[rr[j]];
                float4 e = e4[j];
                e.x *= il; e.y *= il; e.z *= il; e.w *= il;
                __stcs((float4*)(ag + (size_t)rr[j] * SEQL + t * BK + cc[j]), e);
                *(uint2*)(sm + K2_P + rr[j] * 272 + cc[j] * 2) =
                    make_uint2(packh2(e.x, e.y), packh2(e.z, e.w));
            }
        }
        for (int i = tid; i < 1024; i += 256) {
            int kp = i & 63, dm = i >> 6;
            const float* vb = vg + (size_t)(t * BK + 2 * kp) * DH + dm * 4;
            float4 xa = __ldg((const float4*)vb);
            float4 xb = __ldg((const float4*)(vb + DH));
            float fa[4] = {xa.x, xa.y, xa.z, xa.w}, fb[4] = {xb.x, xb.y, xb.z, xb.w};
#pragma unroll
            for (int j = 0; j < 4; ++j) {
                uint32_t hi, lo;
                split2h(fa[j], fb[j], hi, lo);
                *(uint32_t*)(sm + K2_VH + (dm * 4 + j) * 272 + kp * 4) = hi;
                *(uint32_t*)(sm + K2_VL + (dm * 4 + j) * 272 + kp * 4) = lo;
            }
        }
        __syncthreads();

#pragma unroll
        for (int ks = 0; ks < 8; ++ks) {
            uint32_t ah[2][4];
#pragma unroll
            for (int mf = 0; mf < 2; ++mf) {
                int rb = (wm * 32 + mf * 16 + g) * 272 + ks * 32 + t4 * 4;
                ah[mf][0] = *(uint32_t*)(sm + K2_P + rb);
                ah[mf][1] = *(uint32_t*)(sm + K2_P + rb + 8 * 272);
                ah[mf][2] = *(uint32_t*)(sm + K2_P + rb + 16);
                ah[mf][3] = *(uint32_t*)(sm + K2_P + rb + 8 * 272 + 16);
            }
#pragma unroll
            for (int nf = 0; nf < 4; ++nf) {
                int db = (wn * 32 + nf * 8 + g) * 272 + ks * 32 + t4 * 4;
                uint32_t bh0 = *(uint32_t*)(sm + K2_VH + db), bh1 = *(uint32_t*)(sm + K2_VH + db + 16);
                uint32_t bl0 = *(uint32_t*)(sm + K2_VL + db), bl1 = *(uint32_t*)(sm + K2_VL + db + 16);
#pragma unroll
                for (int mf = 0; mf < 2; ++mf) {
                    mma16816h(acc[mf][nf], ah[mf], bh0, bh1);
                    mma16816h(acc[mf][nf], ah[mf], bl0, bl1);
                }
            }
        }
    }
#pragma unroll
    for (int mf = 0; mf < 2; ++mf)
#pragma unroll
        for (int nf = 0; nf < 4; ++nf) {
            int r0 = qb + wm * 32 + mf * 16 + g, d0 = wn * 32 + nf * 8 + t4 * 2;
            float* o = ctx + ((size_t)bh * SEQL + r0) * DH + d0;
            *(float2*)o = make_float2(acc[mf][nf][0], acc[mf][nf][1]);
            *(float2*)(o + 8 * DH) = make_float2(acc[mf][nf][2], acc[mf][nf][3]);
        }
}

extern "C" void kernel_launch(void* const* d_in, const int* in_sizes, int n_in,
                              void* d_out, int out_size) {
    const float* q = (const float*)d_in[0];
    const float* k = (const float*)d_in[1];
    const float* v = (const float*)d_in[2];
    const unsigned char* mask = (const unsigned char*)d_in[3];
    float* out = (float*)d_out;
    float* out_ctx = out;
    float* out_attn = out + (size_t)2 * 16 * SEQL * DH;

    cudaFuncSetAttribute(k1_qk_exp, cudaFuncAttributeMaxDynamicSharedMemorySize, K1_TOT);
    cudaFuncSetAttribute(k2_norm_pv, cudaFuncAttributeMaxDynamicSharedMemorySize, K2_TOT);
    dim3 grid(SEQL / BQ, 32);
    k0_pack_mask<<<(2 * SEQL * (SEQL / 32)) / 256, 256>>>(mask);
    k1_qk_exp<<<grid, 256, K1_TOT>>>(q, k, out_attn);
    k2_norm_pv<<<grid, 256, K2_TOT>>>(v, out_attn, out_ctx);
}

// round 17
// speedup vs baseline: 1.2972x; 1.0140x over previous
#include <cuda_runtime.h>
#include <cuda_bf16.h>
#include <cuda_fp16.h>
#include <cstdint>

#define SEQL 2048
#define DH 64
#define BQ 128
#define BK 128
#define NT 16

__device__ float g_rowsum[2 * 16 * SEQL];
__device__ uint32_t g_mbits[2 * SEQL * (SEQL / 32)];        // 1 MB packed mask bits
__device__ uint32_t g_e[(size_t)2 * 16 * SEQL * (SEQL / 2)]; // 268 MB fp16x2 unnormalized e

#define K1_QH 0
#define K1_QL 18432
#define K1_KH 36864
#define K1_KL 55296
#define K1_RS 73728
#define K1_TOT 74240
// K2: P fp16 (128x136, stride 272B), V^T fp16 hi/lo, inv
#define K2_P  0
#define K2_VH 34816
#define K2_VL 52224
#define K2_INV 69632
#define K2_TOT 70144

static __device__ __forceinline__ float fexp8m(float x) {  // exp(x/8) via ex2.approx
    float t = x * 0.18033688011112042f;
    float r;
    asm("ex2.approx.f32 %0, %1;" : "=f"(r) : "f"(t));
    return r;
}

static __device__ __forceinline__ void split2(float a, float b, uint32_t& hi, uint32_t& lo) {
    __nv_bfloat16 ha = __float2bfloat16_rn(a), hb = __float2bfloat16_rn(b);
    hi = (uint32_t)__bfloat16_as_ushort(ha) | ((uint32_t)__bfloat16_as_ushort(hb) << 16);
    lo = (uint32_t)__bfloat16_as_ushort(__float2bfloat16_rn(a - __bfloat162float(ha))) |
         ((uint32_t)__bfloat16_as_ushort(__float2bfloat16_rn(b - __bfloat162float(hb))) << 16);
}

static __device__ __forceinline__ uint32_t packh2(float a, float b) {
    __half2 h = __floats2half2_rn(a, b);
    return *(uint32_t*)&h;
}
static __device__ __forceinline__ void split2h(float a, float b, uint32_t& hi, uint32_t& lo) {
    __half ha = __float2half_rn(a), hb = __float2half_rn(b);
    hi = (uint32_t)__half_as_ushort(ha) | ((uint32_t)__half_as_ushort(hb) << 16);
    lo = (uint32_t)__half_as_ushort(__float2half_rn(a - __half2float(ha))) |
         ((uint32_t)__half_as_ushort(__float2half_rn(b - __half2float(hb))) << 16);
}

static __device__ __forceinline__ void mma16816(float* c, const uint32_t* a, uint32_t b0, uint32_t b1) {
    asm volatile(
        "mma.sync.aligned.m16n8k16.row.col.f32.bf16.bf16.f32 "
        "{%0,%1,%2,%3}, {%4,%5,%6,%7}, {%8,%9}, {%0,%1,%2,%3};"
        : "+f"(c[0]), "+f"(c[1]), "+f"(c[2]), "+f"(c[3])
        : "r"(a[0]), "r"(a[1]), "r"(a[2]), "r"(a[3]), "r"(b0), "r"(b1));
}
static __device__ __forceinline__ void mma16816h(float* c, const uint32_t* a, uint32_t b0, uint32_t b1) {
    asm volatile(
        "mma.sync.aligned.m16n8k16.row.col.f32.f16.f16.f32 "
        "{%0,%1,%2,%3}, {%4,%5,%6,%7}, {%8,%9}, {%0,%1,%2,%3};"
        : "+f"(c[0]), "+f"(c[1]), "+f"(c[2]), "+f"(c[3])
        : "r"(a[0]), "r"(a[1]), "r"(a[2]), "r"(a[3]), "r"(b0), "r"(b1));
}

static __device__ __forceinline__ void stage64(char* sm, int oh, int ol, const float* g, int tid) {
    for (int i = tid; i < 2048; i += 256) {
        int r = i >> 4, c = (i & 15) * 4;
        float4 x = __ldg((const float4*)(g + r * 64 + c));
        uint32_t h0, l0, h1, l1;
        split2(x.x, x.y, h0, l0); split2(x.z, x.w, h1, l1);
        *(uint2*)(sm + oh + r * 144 + c * 2) = make_uint2(h0, h1);
        *(uint2*)(sm + ol + r * 144 + c * 2) = make_uint2(l0, l1);
    }
}

static __device__ __forceinline__ uint32_t pack4(uint32_t u) {
    return (u & 1u) | ((u >> 7) & 2u) | ((u >> 14) & 4u) | ((u >> 21) & 8u);
}

__global__ void __launch_bounds__(256)
k0_pack_mask(const unsigned char* __restrict__ mask) {
    const int idx = blockIdx.x * 256 + threadIdx.x;
    const uint32_t* mw = (const uint32_t*)mask;
    uint32_t big = 0;
#pragma unroll
    for (int i = 0; i < 16; ++i) big |= (__ldg(mw + i) > 1u) ? 1u : 0u;
    uint32_t wv = 0;
    if (big == 0u) {
        const uint4* p = (const uint4*)(mw + (size_t)idx * 32);
#pragma unroll
        for (int j = 0; j < 8; ++j) {
            uint4 u = __ldg(p + j);
            wv |= ((u.x != 0u) ? 1u : 0u) << (4 * j);
            wv |= ((u.y != 0u) ? 1u : 0u) << (4 * j + 1);
            wv |= ((u.z != 0u) ? 1u : 0u) << (4 * j + 2);
            wv |= ((u.w != 0u) ? 1u : 0u) << (4 * j + 3);
        }
    } else {
        const uint4* p = (const uint4*)(mask + (size_t)idx * 32);
        uint4 u0 = __ldg(p), u1 = __ldg(p + 1);
        wv = pack4(u0.x) | (pack4(u0.y) << 4) | (pack4(u0.z) << 8) | (pack4(u0.w) << 12)
           | (pack4(u1.x) << 16) | (pack4(u1.y) << 20) | (pack4(u1.z) << 24) | (pack4(u1.w) << 28);
    }
    g_mbits[idx] = wv;
}

__global__ void __launch_bounds__(256, 2)
k1_qk_exp(const float* __restrict__ q, const float* __restrict__ k) {
    extern __shared__ char sm[];
    const int tid = threadIdx.x, lane = tid & 31, w = tid >> 5;
    const int g = lane >> 2, t4 = lane & 3, wm = w >> 1, wn = w & 1;
    const int qt = blockIdx.x, bh = blockIdx.y, b = bh >> 4, qb = qt * BQ;
    const float* qg = q + ((size_t)bh * SEQL + qb) * DH;
    const float* kg = k + (size_t)bh * SEQL * DH;
    const uint32_t* mb = g_mbits + (size_t)(b * SEQL + qb) * (SEQL / 32);
    uint32_t* eg = g_e + ((size_t)bh * SEQL + qb) * (SEQL / 2);
    float* rs = (float*)(sm + K1_RS);
    if (tid < 128) rs[tid] = 0.f;
    stage64(sm, K1_QH, K1_QL, qg, tid);

    float rsum[4] = {0.f, 0.f, 0.f, 0.f};

    for (int t = 0; t < NT; ++t) {
        __syncthreads();
        stage64(sm, K1_KH, K1_KL, kg + (size_t)t * BK * DH, tid);
        __syncthreads();

        float acc[2][8][4];
#pragma unroll
        for (int mf = 0; mf < 2; ++mf)
#pragma unroll
            for (int nf = 0; nf < 8; ++nf)
#pragma unroll
                for (int e = 0; e < 4; ++e) acc[mf][nf][e] = 0.f;

#pragma unroll
        for (int ks = 0; ks < 4; ++ks) {
            uint32_t ah[2][4], al[2][4];
#pragma unroll
            for (int mf = 0; mf < 2; ++mf) {
                int rb = (wm * 32 + mf * 16 + g) * 144 + ks * 32 + t4 * 4;
                ah[mf][0] = *(uint32_t*)(sm + K1_QH + rb);
                ah[mf][1] = *(uint32_t*)(sm + K1_QH + rb + 8 * 144);
                ah[mf][2] = *(uint32_t*)(sm + K1_QH + rb + 16);
                ah[mf][3] = *(uint32_t*)(sm + K1_QH + rb + 8 * 144 + 16);
                al[mf][0] = *(uint32_t*)(sm + K1_QL + rb);
                al[mf][1] = *(uint32_t*)(sm + K1_QL + rb + 8 * 144);
                al[mf][2] = *(uint32_t*)(sm + K1_QL + rb + 16);
                al[mf][3] = *(uint32_t*)(sm + K1_QL + rb + 8 * 144 + 16);
            }
#pragma unroll
            for (int nf = 0; nf < 8; ++nf) {
                int cb = (wn * 64 + nf * 8 + g) * 144 + ks * 32 + t4 * 4;
                uint32_t bh0 = *(uint32_t*)(sm + K1_KH + cb), bh1 = *(uint32_t*)(sm + K1_KH + cb + 16);
                uint32_t bl0 = *(uint32_t*)(sm + K1_KL + cb), bl1 = *(uint32_t*)(sm + K1_KL + cb + 16);
#pragma unroll
                for (int mf = 0; mf < 2; ++mf) {
                    mma16816(acc[mf][nf], ah[mf], bh0, bh1);
                    mma16816(acc[mf][nf], ah[mf], bl0, bl1);
                    mma16816(acc[mf][nf], al[mf], bh0, bh1);
                }
            }
        }

#pragma unroll
        for (int mf = 0; mf < 2; ++mf) {
            int r0 = wm * 32 + mf * 16 + g;
            const uint32_t* ra = mb + (size_t)r0 * (SEQL / 32) + t * 4 + wn * 2;
            const uint32_t* rb2 = mb + (size_t)(r0 + 8) * (SEQL / 32) + t * 4 + wn * 2;
            uint32_t wa0 = __ldg(ra), wa1 = __ldg(ra + 1);
            uint32_t wb0 = __ldg(rb2), wb1 = __ldg(rb2 + 1);
#pragma unroll
            for (int nf = 0; nf < 8; ++nf) {
                int c0 = wn * 64 + nf * 8 + t4 * 2;
                int sh = (nf & 3) * 8 + t4 * 2;
                uint32_t ma = ((nf >> 2) ? wa1 : wa0) >> sh;
                uint32_t mbv = ((nf >> 2) ? wb1 : wb0) >> sh;
                float e0 = (ma & 1u)  ? fexp8m(acc[mf][nf][0]) : 1.0f;
                float e1 = (ma & 2u)  ? fexp8m(acc[mf][nf][1]) : 1.0f;
                float e2 = (mbv & 1u) ? fexp8m(acc[mf][nf][2]) : 1.0f;
                float e3 = (mbv & 2u) ? fexp8m(acc[mf][nf][3]) : 1.0f;
                rsum[mf * 2] += e0 + e1;
                rsum[mf * 2 + 1] += e2 + e3;
                uint32_t* d = eg + (size_t)r0 * (SEQL / 2) + (t * BK + c0) / 2;
                __stcs(d, packh2(e0, e1));
                __stcs(d + 8 * (SEQL / 2), packh2(e2, e3));
            }
        }
    }

#pragma unroll
    for (int i = 0; i < 4; ++i) {
        rsum[i] += __shfl_xor_sync(~0u, rsum[i], 1);
        rsum[i] += __shfl_xor_sync(~0u, rsum[i], 2);
    }
    if (t4 == 0) {
        atomicAdd(&rs[wm * 32 + g], rsum[0]);
        atomicAdd(&rs[wm * 32 + g + 8], rsum[1]);
        atomicAdd(&rs[wm * 32 + 16 + g], rsum[2]);
        atomicAdd(&rs[wm * 32 + 24 + g], rsum[3]);
    }
    __syncthreads();
    if (tid < 128) g_rowsum[(size_t)bh * SEQL + qb + tid] = rs[tid];
}

__global__ void __launch_bounds__(256, 2)
k2_norm_pv(const float* __restrict__ v, float* __restrict__ attn, float* __restrict__ ctx) {
    extern __shared__ char sm[];
    const int tid = threadIdx.x, lane = tid & 31, w = tid >> 5;
    const int g = lane >> 2, t4 = lane & 3, wm = w >> 1, wn = w & 1;
    const int qt = blockIdx.x, bh = blockIdx.y, qb = qt * BQ;
    float* ag = attn + ((size_t)bh * SEQL + qb) * SEQL;
    const uint32_t* eg = g_e + ((size_t)bh * SEQL + qb) * (SEQL / 2);
    const float* vg = v + (size_t)bh * SEQL * DH;
    float* inv = (float*)(sm + K2_INV);
    if (tid < 128)
        inv[tid] = 1.0f / fmaxf(g_rowsum[(size_t)bh * SEQL + qb + tid], 1e-30f);

    float acc[2][4][4];
#pragma unroll
    for (int mf = 0; mf < 2; ++mf)
#pragma unroll
        for (int nf = 0; nf < 4; ++nf)
#pragma unroll
            for (int e = 0; e < 4; ++e) acc[mf][nf][e] = 0.f;

    for (int t = 0; t < NT; ++t) {
        __syncthreads();
        // read fp16 e (batched MLP=4), normalize, write fp32 attention, stage fp16 P
#pragma unroll
        for (int ii = 0; ii < 16; ii += 4) {
            uint2 ev[4];
            int rr[4], cc[4];
#pragma unroll
            for (int j = 0; j < 4; ++j) {
                int i = (ii + j) * 256 + tid;
                rr[j] = i >> 5; cc[j] = (i & 31) * 4;
                ev[j] = __ldcs((const uint2*)(eg + (size_t)rr[j] * (SEQL / 2) + (t * BK + cc[j]) / 2));
            }
#pragma unroll
            for (int j = 0; j < 4; ++j) {
                float il = inv[rr[j]];
                __half2 h01 = *(__half2*)&ev[j].x, h23 = *(__half2*)&ev[j].y;
                float2 f01 = __half22float2(h01), f23 = __half22float2(h23);
                float p0 = f01.x * il, p1 = f01.y * il, p2 = f23.x * il, p3 = f23.y * il;
                __stcs((float4*)(ag + (size_t)rr[j] * SEQL + t * BK + cc[j]),
                       make_float4(p0, p1, p2, p3));
                *(uint2*)(sm + K2_P + rr[j] * 272 + cc[j] * 2) =
                    make_uint2(packh2(p0, p1), packh2(p2, p3));
            }
        }
        for (int i = tid; i < 1024; i += 256) {
            int kp = i & 63, dm = i >> 6;
            const float* vb = vg + (size_t)(t * BK + 2 * kp) * DH + dm * 4;
            float4 xa = __ldg((const float4*)vb);
            float4 xb = __ldg((const float4*)(vb + DH));
            float fa[4] = {xa.x, xa.y, xa.z, xa.w}, fb[4] = {xb.x, xb.y, xb.z, xb.w};
#pragma unroll
            for (int j = 0; j < 4; ++j) {
                uint32_t hi, lo;
                split2h(fa[j], fb[j], hi, lo);
                *(uint32_t*)(sm + K2_VH + (dm * 4 + j) * 272 + kp * 4) = hi;
                *(uint32_t*)(sm + K2_VL + (dm * 4 + j) * 272 + kp * 4) = lo;
            }
        }
        __syncthreads();

#pragma unroll
        for (int ks = 0; ks < 8; ++ks) {
            uint32_t ah[2][4];
#pragma unroll
            for (int mf = 0; mf < 2; ++mf) {
                int rb = (wm * 32 + mf * 16 + g) * 272 + ks * 32 + t4 * 4;
                ah[mf][0] = *(uint32_t*)(sm + K2_P + rb);
                ah[mf][1] = *(uint32_t*)(sm + K2_P + rb + 8 * 272);
                ah[mf][2] = *(uint32_t*)(sm + K2_P + rb + 16);
                ah[mf][3] = *(uint32_t*)(sm + K2_P + rb + 8 * 272 + 16);
            }
#pragma unroll
            for (int nf = 0; nf < 4; ++nf) {
                int db = (wn * 32 + nf * 8 + g) * 272 + ks * 32 + t4 * 4;
                uint32_t bh0 = *(uint32_t*)(sm + K2_VH + db), bh1 = *(uint32_t*)(sm + K2_VH + db + 16);
                uint32_t bl0 = *(uint32_t*)(sm + K2_VL + db), bl1 = *(uint32_t*)(sm + K2_VL + db + 16);
#pragma unroll
                for (int mf = 0; mf < 2; ++mf) {
                    mma16816h(acc[mf][nf], ah[mf], bh0, bh1);
                    mma16816h(acc[mf][nf], ah[mf], bl0, bl1);
                }
            }
        }
    }
#pragma unroll
    for (int mf = 0; mf < 2; ++mf)
#pragma unroll
        for (int nf = 0; nf < 4; ++nf) {
            int r0 = qb + wm * 32 + mf * 16 + g, d0 = wn * 32 + nf * 8 + t4 * 2;
            float* o = ctx + ((size_t)bh * SEQL + r0) * DH + d0;
            *(float2*)o = make_float2(acc[mf][nf][0], acc[mf][nf][1]);
            *(float2*)(o + 8 * DH) = make_float2(acc[mf][nf][2], acc[mf][nf][3]);
        }
}

extern "C" void kernel_launch(void* const* d_in, const int* in_sizes, int n_in,
                              void* d_out, int out_size) {
    const float* q = (const float*)d_in[0];
    const float* k = (const float*)d_in[1];
    const float* v = (const float*)d_in[2];
    const unsigned char* mask = (const unsigned char*)d_in[3];
    float* out = (float*)d_out;
    float* out_ctx = out;
    float* out_attn = out + (size_t)2 * 16 * SEQL * DH;

    cudaFuncSetAttribute(k1_qk_exp, cudaFuncAttributeMaxDynamicSharedMemorySize, K1_TOT);
    cudaFuncSetAttribute(k2_norm_pv, cudaFuncAttributeMaxDynamicSharedMemorySize, K2_TOT);
    dim3 grid(SEQL / BQ, 32);
    k0_pack_mask<<<(2 * SEQL * (SEQL / 32)) / 256, 256>>>(mask);
    k1_qk_exp<<<grid, 256, K1_TOT>>>(q, k);
    k2_norm_pv<<<grid, 256, K2_TOT>>>(v, out_attn, out_ctx);
}